// round 11
// baseline (speedup 1.0000x reference)
#include <cuda_runtime.h>
#include <cuda_bf16.h>
#include <cstdint>

// ============================================================================
// Int8Linear: out[8192,4096] = x[8192,4096] @ W^T[4096,4096] + bias
// R11: native int8 tensor path (mma.sync.m16n8k32.s8) — 4x MACs/instruction
// vs tf32 k8. W feeds the MMA as EXACT int8; per-(n,k64)-block scale applied
// in fp32 outside the (exact) int32 accumulation. x is decomposed into two
// int8 digits (15-bit fixed point, fixed scale sx = 8/16256):
//   out[m,n] = sx * sum_b sw[n,b] * (128*Ahi[m,n,b] + Alo[m,n,b]) + bias[n]
// where Ahi/Alo are exact int32 dot products over each 64-k block.
// Expected rel_err ~1.4e-4 (x quantization only; everything else exact/fp32).
//
//   Pass 0: detect weight dtype (int8 vs int32-promoted)
//   Pass 1: digitize x -> hi/lo int8 planes, k-permuted, scratch gA
//   Pass 2: pack W -> int8, k-permuted, scratch gW
//   Pass 3: transpose scales -> scaleT[b][n]
//   Pass 4: GEMM: CTA 128x128, 16 warps (4x4), warp tile 32x32, KT=64,
//           3-stage cp.async, s8 MMAs with per-k64 fp32 rescale, fused bias.
// k-permutation: within each 64B k-block, u32 p holds logical k-group
// g = (p&3)*4 + (p>>2), so one LDS.128 per thread yields the s8 fragments
// for BOTH k32 MMAs of the block.
// ============================================================================

#define M_DIM  8192
#define N_DIM  4096
#define K_DIM  4096
#define NUM_KB (K_DIM / 64)   // 64 k-blocks
#define STAGES 3

// scratch
__device__ __align__(16) uint32_t g_xa[(size_t)M_DIM * K_DIM * 2 / 4]; // x digits (hi,lo)
__device__ __align__(16) uint32_t g_wp[(size_t)N_DIM * K_DIM / 4];     // W int8 packed
__device__ float g_scaleT[(size_t)NUM_KB * N_DIM];                     // scales [b][n]
__device__ int g_w_is_i32;

#define SX (8.0f / 16256.0f)
#define INV_SX 2032.0f

// ---------------------------------------------------------------- helpers
__device__ __forceinline__ uint32_t smem_u32(const void* p) {
    uint32_t a;
    asm("{ .reg .u64 t; cvta.to.shared.u64 t, %1; cvt.u32.u64 %0, t; }" : "=r"(a) : "l"(p));
    return a;
}
__device__ __forceinline__ void cp_async16(uint32_t dst, const void* src) {
    asm volatile("cp.async.cg.shared.global [%0], [%1], 16;" :: "r"(dst), "l"(src));
}
#define CP_COMMIT() asm volatile("cp.async.commit_group;" ::: "memory")
#define CP_WAIT1()  asm volatile("cp.async.wait_group 1;" ::: "memory")

// s8 MMA, C = 0 (zero regs read-only)
__device__ __forceinline__ void mma_s8_zc(int (&d)[4], uint32_t a0, uint32_t a1,
                                          uint32_t a2, uint32_t a3,
                                          uint32_t b0, uint32_t b1) {
    asm volatile(
        "mma.sync.aligned.m16n8k32.row.col.s32.s8.s8.s32 "
        "{%0,%1,%2,%3}, {%4,%5,%6,%7}, {%8,%9}, {%10,%11,%12,%13};"
        : "=r"(d[0]), "=r"(d[1]), "=r"(d[2]), "=r"(d[3])
        : "r"(a0), "r"(a1), "r"(a2), "r"(a3), "r"(b0), "r"(b1),
          "r"(0), "r"(0), "r"(0), "r"(0));
}
// s8 MMA, accumulate in place
__device__ __forceinline__ void mma_s8_acc(int (&d)[4], uint32_t a0, uint32_t a1,
                                           uint32_t a2, uint32_t a3,
                                           uint32_t b0, uint32_t b1) {
    asm volatile(
        "mma.sync.aligned.m16n8k32.row.col.s32.s8.s8.s32 "
        "{%0,%1,%2,%3}, {%4,%5,%6,%7}, {%8,%9}, {%0,%1,%2,%3};"
        : "+r"(d[0]), "+r"(d[1]), "+r"(d[2]), "+r"(d[3])
        : "r"(a0), "r"(a1), "r"(a2), "r"(a3), "r"(b0), "r"(b1));
}

// ---------------------------------------------------------------- dtype probe
__global__ void detect_wtype_kernel(const int* __restrict__ w) {
    __shared__ int s_ok;
    if (threadIdx.x == 0) s_ok = 1;
    __syncthreads();
    #pragma unroll
    for (int i = 0; i < 4; i++) {
        int v = w[threadIdx.x + i * 256];
        if (v < -128 || v > 127) atomicAnd(&s_ok, 0);
    }
    __syncthreads();
    if (threadIdx.x == 0) g_w_is_i32 = s_ok;
}

// ---------------------------------------------------------------- preprocess
// One thread per (m, b): 64 k-values -> hi/lo int8, written k-permuted.
// Scratch layout: u32 offset = (chunk*2 + digit)*16 + p, chunk = m*64+b.
__global__ void digitize_x_kernel(const float4* __restrict__ x, uint4* __restrict__ out,
                                  int nchunk) {
    for (int c = blockIdx.x * blockDim.x + threadIdx.x; c < nchunk;
         c += gridDim.x * blockDim.x) {
        int8_t hi[64], lo[64];
        #pragma unroll
        for (int j = 0; j < 16; j++) {
            float4 v = x[c * 16 + j];
            float f[4] = {v.x, v.y, v.z, v.w};
            #pragma unroll
            for (int t = 0; t < 4; t++) {
                float xs = fminf(fmaxf(f[t] * INV_SX, -16256.0f), 16256.0f);
                int qi = __float2int_rn(xs);
                int h = (qi + 64) >> 7;
                hi[j * 4 + t] = (int8_t)h;
                lo[j * 4 + t] = (int8_t)(qi - (h << 7));
            }
        }
        uint32_t hw[16], lw[16];
        #pragma unroll
        for (int p = 0; p < 16; p++) {
            int g = (p & 3) * 4 + (p >> 2);   // logical k-group for phys slot p
            hw[p] = (uint32_t)(uint8_t)hi[4 * g] | ((uint32_t)(uint8_t)hi[4 * g + 1] << 8) |
                    ((uint32_t)(uint8_t)hi[4 * g + 2] << 16) | ((uint32_t)(uint8_t)hi[4 * g + 3] << 24);
            lw[p] = (uint32_t)(uint8_t)lo[4 * g] | ((uint32_t)(uint8_t)lo[4 * g + 1] << 8) |
                    ((uint32_t)(uint8_t)lo[4 * g + 2] << 16) | ((uint32_t)(uint8_t)lo[4 * g + 3] << 24);
        }
        uint4* o = out + (size_t)c * 8;   // 2 digits * 4 uint4
        #pragma unroll
        for (int j = 0; j < 4; j++) o[j]     = make_uint4(hw[4*j], hw[4*j+1], hw[4*j+2], hw[4*j+3]);
        #pragma unroll
        for (int j = 0; j < 4; j++) o[4 + j] = make_uint4(lw[4*j], lw[4*j+1], lw[4*j+2], lw[4*j+3]);
    }
}

// One thread per (n, b): pack 64 weights to int8, k-permuted.
__global__ void pack_w_kernel(const void* __restrict__ wsrc, uint4* __restrict__ out,
                              int nchunk) {
    const bool i32 = (g_w_is_i32 != 0);
    for (int c = blockIdx.x * blockDim.x + threadIdx.x; c < nchunk;
         c += gridDim.x * blockDim.x) {
        uint32_t wrd[16];
        if (i32) {
            const int4* p = (const int4*)wsrc + (size_t)c * 16;
            #pragma unroll
            for (int g = 0; g < 16; g++) {
                int4 v = p[g];   // 4 ints = logical k 4g..4g+3
                wrd[g] = (uint32_t)(uint8_t)(int8_t)v.x | ((uint32_t)(uint8_t)(int8_t)v.y << 8) |
                         ((uint32_t)(uint8_t)(int8_t)v.z << 16) | ((uint32_t)(uint8_t)(int8_t)v.w << 24);
            }
        } else {
            const uint32_t* p = (const uint32_t*)wsrc + (size_t)c * 16;
            #pragma unroll
            for (int g = 0; g < 16; g++) wrd[g] = p[g];
        }
        uint32_t o[16];
        #pragma unroll
        for (int p = 0; p < 16; p++) o[p] = wrd[(p & 3) * 4 + (p >> 2)];
        uint4* op = out + (size_t)c * 4;
        #pragma unroll
        for (int j = 0; j < 4; j++) op[j] = make_uint4(o[4*j], o[4*j+1], o[4*j+2], o[4*j+3]);
    }
}

// scaleT[b*4096 + n] = scales[n*64 + b]
__global__ void transpose_scales_kernel(const float* __restrict__ s, float* __restrict__ st) {
    int i = blockIdx.x * blockDim.x + threadIdx.x;
    if (i < NUM_KB * N_DIM) {
        int n = i >> 6, b = i & 63;
        st[(size_t)b * N_DIM + n] = s[i];
    }
}

// ---------------------------------------------------------------- GEMM
static constexpr int A_STAGE_U32 = 128 * 2 * 16;              // 4096 u32 = 16KB
static constexpr int B_STAGE_U32 = 128 * 16;                  // 2048 u32 = 8KB
static constexpr int STAGE_U32   = A_STAGE_U32 + B_STAGE_U32; // 6144 u32 = 24KB
static constexpr int SMEM_TOTAL  = STAGES * STAGE_U32 * 4;    // 73728 B

__global__ void __launch_bounds__(512, 1)
gemm_s8_kernel(const uint32_t* __restrict__ gA, const uint32_t* __restrict__ gW,
               const float* __restrict__ scaleT, const float* __restrict__ bias,
               float* __restrict__ out) {
    extern __shared__ uint32_t smem[];
    const uint32_t sb = smem_u32(smem);
    const int tid = threadIdx.x, wid = tid >> 5, lid = tid & 31;
    const int gid = lid >> 2, tig = lid & 3;
    const int wr = wid & 3;          // warp m index: 0..3 (32 rows)
    const int wcc = wid >> 2;        // warp n index: 0..3 (32 cols)
    const int bm = blockIdx.y, bn = blockIdx.x;

    // loader: A = 1024 chunks (128 rows x 2 digits x 4 q), B = 512 chunks
    auto load_tile = [&](int t, int s) {
        const uint32_t sA = sb + s * STAGE_U32 * 4;
        const uint32_t sB = sA + A_STAGE_U32 * 4;
        #pragma unroll
        for (int i = 0; i < 2; i++) {
            int c = tid + i * 512;
            int r = c >> 3, sub = c & 7;
            int d = sub >> 2, q = sub & 3;
            const uint32_t* src = gA + ((((size_t)(bm * 128 + r) * 64 + t) * 2 + d) * 16 + q * 4);
            cp_async16(sA + (uint32_t)((r * 8 + (d ^ (r & 1)) * 4 + q) * 16), src);
        }
        {
            int r = tid >> 2, q = tid & 3;
            const uint32_t* src = gW + (((size_t)(bn * 128 + r) * 64 + t) * 16 + q * 4);
            cp_async16(sB + (uint32_t)((r * 4 + q) * 16), src);
        }
    };

    float facc[2][4][4];
    #pragma unroll
    for (int mt = 0; mt < 2; mt++)
        #pragma unroll
        for (int nt = 0; nt < 4; nt++)
            #pragma unroll
            for (int c = 0; c < 4; c++) facc[mt][nt][c] = 0.0f;

    load_tile(0, 0); CP_COMMIT();
    load_tile(1, 1); CP_COMMIT();

    int cs = 0, ls = 2;
    for (int kt = 0; kt < NUM_KB; kt++) {
        CP_WAIT1();
        __syncthreads();

        const int tl = kt + 2;
        if (tl < NUM_KB) load_tile(tl, ls);
        CP_COMMIT();

        const uint4* sA4 = reinterpret_cast<const uint4*>(smem + cs * STAGE_U32);
        const uint4* sB4 = reinterpret_cast<const uint4*>(smem + cs * STAGE_U32 + A_STAGE_U32);

        // block scales for this warp's n-columns
        const float* stp = scaleT + (size_t)kt * N_DIM + bn * 128 + wcc * 32 + 2 * tig;
        float2 sv[4];
        #pragma unroll
        for (int nt = 0; nt < 4; nt++) sv[nt] = *reinterpret_cast<const float2*>(stp + nt * 8);

        // B fragments (both k32 halves in one LDS.128)
        uint4 Bv[4];
        #pragma unroll
        for (int nt = 0; nt < 4; nt++)
            Bv[nt] = sB4[(wcc * 32 + nt * 8 + gid) * 4 + tig];

        // ---- hi digit (d=0) ----
        {
            uint4 Av[2][2];
            #pragma unroll
            for (int mt = 0; mt < 2; mt++)
                #pragma unroll
                for (int h = 0; h < 2; h++) {
                    int row = wr * 32 + mt * 16 + h * 8 + gid;
                    Av[mt][h] = sA4[row * 8 + (row & 1) * 4 + tig];   // d=0 -> slot row&1
                }
            #pragma unroll
            for (int mt = 0; mt < 2; mt++)
                #pragma unroll
                for (int nt = 0; nt < 4; nt++) {
                    int u[4];
                    mma_s8_zc(u, Av[mt][0].x, Av[mt][1].x, Av[mt][0].y, Av[mt][1].y,
                              Bv[nt].x, Bv[nt].y);
                    mma_s8_acc(u, Av[mt][0].z, Av[mt][1].z, Av[mt][0].w, Av[mt][1].w,
                               Bv[nt].z, Bv[nt].w);
                    float f0 = sv[nt].x * 128.0f, f1 = sv[nt].y * 128.0f;
                    facc[mt][nt][0] += (float)u[0] * f0;
                    facc[mt][nt][1] += (float)u[1] * f1;
                    facc[mt][nt][2] += (float)u[2] * f0;
                    facc[mt][nt][3] += (float)u[3] * f1;
                }
        }
        // ---- lo digit (d=1) ----
        {
            uint4 Av[2][2];
            #pragma unroll
            for (int mt = 0; mt < 2; mt++)
                #pragma unroll
                for (int h = 0; h < 2; h++) {
                    int row = wr * 32 + mt * 16 + h * 8 + gid;
                    Av[mt][h] = sA4[row * 8 + ((row & 1) ^ 1) * 4 + tig]; // d=1
                }
            #pragma unroll
            for (int mt = 0; mt < 2; mt++)
                #pragma unroll
                for (int nt = 0; nt < 4; nt++) {
                    int u[4];
                    mma_s8_zc(u, Av[mt][0].x, Av[mt][1].x, Av[mt][0].y, Av[mt][1].y,
                              Bv[nt].x, Bv[nt].y);
                    mma_s8_acc(u, Av[mt][0].z, Av[mt][1].z, Av[mt][0].w, Av[mt][1].w,
                               Bv[nt].z, Bv[nt].w);
                    facc[mt][nt][0] += (float)u[0] * sv[nt].x;
                    facc[mt][nt][1] += (float)u[1] * sv[nt].y;
                    facc[mt][nt][2] += (float)u[2] * sv[nt].x;
                    facc[mt][nt][3] += (float)u[3] * sv[nt].y;
                }
        }

        if (++cs == STAGES) cs = 0;
        if (++ls == STAGES) ls = 0;
    }

    // epilogue: out = SX * facc + bias
    #pragma unroll
    for (int mt = 0; mt < 2; mt++) {
        #pragma unroll
        for (int nt = 0; nt < 4; nt++) {
            const int n0 = bn * 128 + wcc * 32 + nt * 8 + 2 * tig;
            const float b0 = __ldg(bias + n0), b1 = __ldg(bias + n0 + 1);
            #pragma unroll
            for (int half = 0; half < 2; half++) {
                const int grow = bm * 128 + wr * 32 + mt * 16 + gid + half * 8;
                float2 o;
                o.x = SX * facc[mt][nt][half * 2 + 0] + b0;
                o.y = SX * facc[mt][nt][half * 2 + 1] + b1;
                *reinterpret_cast<float2*>(out + (size_t)grow * N_DIM + n0) = o;
            }
        }
    }
}

// ---------------------------------------------------------------- launcher
extern "C" void kernel_launch(void* const* d_in, const int* in_sizes, int n_in,
                              void* d_out, int out_size) {
    // Resolve inputs BY SIZE (unique element counts).
    const float* x      = nullptr;
    const void*  qw     = nullptr;
    const float* scales = nullptr;
    const float* bias   = nullptr;
    for (int i = 0; i < n_in; i++) {
        switch (in_sizes[i]) {
            case 33554432: x      = (const float*)d_in[i]; break;
            case 16777216: qw     = d_in[i];               break;
            case 262144:   scales = (const float*)d_in[i]; break;
            case 4096:     bias   = (const float*)d_in[i]; break;
            default: break;
        }
    }
    float* out = (float*)d_out;

    uint32_t* gA; cudaGetSymbolAddress((void**)&gA, g_xa);
    uint32_t* gW; cudaGetSymbolAddress((void**)&gW, g_wp);
    float* gST;   cudaGetSymbolAddress((void**)&gST, g_scaleT);

    detect_wtype_kernel<<<1, 256>>>((const int*)qw);
    digitize_x_kernel<<<2048, 256>>>((const float4*)x, (uint4*)gA, (M_DIM * K_DIM) / 64);
    pack_w_kernel<<<1024, 256>>>(qw, (uint4*)gW, (N_DIM * K_DIM) / 64);
    transpose_scales_kernel<<<(NUM_KB * N_DIM + 255) / 256, 256>>>(scales, gST);

    cudaFuncSetAttribute(gemm_s8_kernel, cudaFuncAttributeMaxDynamicSharedMemorySize, SMEM_TOTAL);
    dim3 grid(N_DIM / 128, M_DIM / 128);   // (32, 64)
    gemm_s8_kernel<<<grid, 512, SMEM_TOTAL>>>(gA, gW, gST, bias, out);
}

// round 13
// speedup vs baseline: 2.5100x; 2.5100x over previous
#include <cuda_runtime.h>
#include <cuda_bf16.h>
#include <cstdint>

// ============================================================================
// Int8Linear: out[8192,4096] = x[8192,4096] @ W^T[4096,4096] + bias
// R12: back to the tf32 path (R11's s8 experiment proved the per-k64 fp32
// rescale floods the scalar pipes: 4026us). R10 base (1557us, tensor=60.8%,
// alu=30.4%) with the mainloop address arithmetic HOISTED:
//   - thread fragment-row parity is uniform -> only two swizzled columns
//     (c1 = c0^4); precompute 4 base addresses per stage (A/B x ks2).
//   - k-loop unrolled in triples so the stage index is compile-time; all 24
//     LDS.128 per iteration become [reg + immediate].
//   - loader src/dst offsets precomputed per thread.
// MMA order identical to R10 -> rel_err canary 2.937228e-4 (bit-exact).
// ============================================================================

#define M_DIM  8192
#define N_DIM  4096
#define K_DIM  4096
#define MT     128
#define NT     128
#define KT     32
#define NUM_KT (K_DIM / KT)   // 128
#define STAGES 3

__device__ __align__(16) uint32_t g_xa[(size_t)M_DIM * K_DIM];  // x, tf32, k-permuted
__device__ __align__(16) uint32_t g_wb[(size_t)N_DIM * K_DIM];  // W,  tf32, k-permuted
__device__ int g_w_is_i32;

// ---------------------------------------------------------------- helpers
__device__ __forceinline__ uint32_t smem_u32(const void* p) {
    uint32_t a;
    asm("{ .reg .u64 t; cvta.to.shared.u64 t, %1; cvt.u32.u64 %0, t; }" : "=r"(a) : "l"(p));
    return a;
}
__device__ __forceinline__ uint32_t f2tf32(float f) {
    uint32_t r; asm("cvt.rna.tf32.f32 %0, %1;" : "=r"(r) : "f"(f)); return r;
}
__device__ __forceinline__ void cp_async16(uint32_t dst, const void* src) {
    asm volatile("cp.async.cg.shared.global [%0], [%1], 16;" :: "r"(dst), "l"(src));
}
#define CP_COMMIT() asm volatile("cp.async.commit_group;" ::: "memory")
#define CP_WAIT1()  asm volatile("cp.async.wait_group 1;" ::: "memory")

__device__ __forceinline__ void lds128(uint4& v, uint32_t addr) {
    asm volatile("ld.shared.v4.b32 {%0,%1,%2,%3}, [%4];"
                 : "=r"(v.x), "=r"(v.y), "=r"(v.z), "=r"(v.w) : "r"(addr));
}

__device__ __forceinline__ void mma_tf32(float (&d)[4], const uint32_t (&a)[4],
                                         const uint32_t (&b)[2]) {
    asm volatile(
        "mma.sync.aligned.m16n8k8.row.col.f32.tf32.tf32.f32 "
        "{%0,%1,%2,%3}, {%4,%5,%6,%7}, {%8,%9}, {%0,%1,%2,%3};"
        : "+f"(d[0]), "+f"(d[1]), "+f"(d[2]), "+f"(d[3])
        : "r"(a[0]), "r"(a[1]), "r"(a[2]), "r"(a[3]), "r"(b[0]), "r"(b[1]));
}

// ---------------------------------------------------------------- dtype probe
__global__ void detect_wtype_kernel(const int* __restrict__ w) {
    __shared__ int s_ok;
    if (threadIdx.x == 0) s_ok = 1;
    __syncthreads();
    #pragma unroll
    for (int i = 0; i < 4; i++) {
        int v = w[threadIdx.x + i * 256];
        if (v < -128 || v > 127) atomicAnd(&s_ok, 0);
    }
    __syncthreads();
    if (threadIdx.x == 0) g_w_is_i32 = s_ok;
}

// ---------------------------------------------------------------- preprocess
// 16-k block permuted: phys float4 p = (w[p], w[p+4], w[p+8], w[p+12]).
__global__ void cvt_x_kernel(const float4* __restrict__ x, uint4* __restrict__ out, int nblk) {
    for (int b = blockIdx.x * blockDim.x + threadIdx.x; b < nblk; b += gridDim.x * blockDim.x) {
        float4 v0 = x[b * 4 + 0], v1 = x[b * 4 + 1], v2 = x[b * 4 + 2], v3 = x[b * 4 + 3];
        uint4 o;
        o.x = f2tf32(v0.x); o.y = f2tf32(v1.x); o.z = f2tf32(v2.x); o.w = f2tf32(v3.x);
        out[b * 4 + 0] = o;
        o.x = f2tf32(v0.y); o.y = f2tf32(v1.y); o.z = f2tf32(v2.y); o.w = f2tf32(v3.y);
        out[b * 4 + 1] = o;
        o.x = f2tf32(v0.z); o.y = f2tf32(v1.z); o.z = f2tf32(v2.z); o.w = f2tf32(v3.z);
        out[b * 4 + 2] = o;
        o.x = f2tf32(v0.w); o.y = f2tf32(v1.w); o.z = f2tf32(v2.w); o.w = f2tf32(v3.w);
        out[b * 4 + 3] = o;
    }
}

__global__ void dequant_w_kernel(const void* __restrict__ wsrc, const float* __restrict__ scales,
                                 uint4* __restrict__ out, int nblk) {
    const bool i32 = (g_w_is_i32 != 0);
    for (int b = blockIdx.x * blockDim.x + threadIdx.x; b < nblk; b += gridDim.x * blockDim.x) {
        float s = __ldg(scales + (b >> 2));
        float w[16];
        if (i32) {
            const int4* p = (const int4*)wsrc + b * 4;
            #pragma unroll
            for (int j = 0; j < 4; j++) {
                int4 v = p[j];
                w[j * 4 + 0] = (float)v.x; w[j * 4 + 1] = (float)v.y;
                w[j * 4 + 2] = (float)v.z; w[j * 4 + 3] = (float)v.w;
            }
        } else {
            uint4 raw = ((const uint4*)wsrc)[b];
            uint32_t ws[4] = {raw.x, raw.y, raw.z, raw.w};
            #pragma unroll
            for (int j = 0; j < 4; j++)
                #pragma unroll
                for (int t = 0; t < 4; t++)
                    w[j * 4 + t] = (float)(int8_t)((ws[j] >> (8 * t)) & 0xFF);
        }
        #pragma unroll
        for (int p = 0; p < 4; p++) {
            uint4 o;
            o.x = f2tf32(s * w[p]);      o.y = f2tf32(s * w[p + 4]);
            o.z = f2tf32(s * w[p + 8]);  o.w = f2tf32(s * w[p + 12]);
            out[b * 4 + p] = o;
        }
    }
}

// ---------------------------------------------------------------- GEMM
static constexpr int A_STAGE_U32 = MT * KT;                   // 4096 u32 = 16KB
static constexpr int B_STAGE_U32 = NT * KT;                   // 4096 u32
static constexpr int STAGE_U32   = A_STAGE_U32 + B_STAGE_U32; // 8192 u32 = 32KB
static constexpr int STAGE_BYTES = STAGE_U32 * 4;
static constexpr int SMEM_TOTAL  = STAGES * STAGE_BYTES;      // 98304 B -> 2 CTA/SM

__global__ void __launch_bounds__(256, 2)
gemm_tf32_kernel(const uint32_t* __restrict__ gA, const uint32_t* __restrict__ gB,
                 const float* __restrict__ bias, float* __restrict__ out) {
    extern __shared__ uint32_t smem[];
    const uint32_t sb = smem_u32(smem);
    const int tid = threadIdx.x, wid = tid >> 5, lid = tid & 31;
    const int wr = wid & 3;          // warp row (m): 0..3
    const int wc = wid >> 2;         // warp col (n): 0..1
    const int bm = blockIdx.y, bn = blockIdx.x;

    const uint32_t* gAt0 = gA + (size_t)bm * MT * K_DIM;
    const uint32_t* gBt0 = gB + (size_t)bn * NT * K_DIM;

    // ---- hoisted loader offsets (thread-const) ----
    uint32_t dstOff[4];          // SMEM byte offset within a plane
    uint32_t srcOff[4];          // u32 element offset within a tile row-block
    #pragma unroll
    for (int i = 0; i < 4; i++) {
        int ch = tid + i * 256;
        int r = ch >> 3, c4 = ch & 7;
        dstOff[i] = (uint32_t)((r * 8 + (c4 ^ ((r & 1) << 2))) * 16);
        srcOff[i] = (uint32_t)(r * K_DIM + c4 * 4);
    }

    auto load_tile = [&](int t, uint32_t stage_byte) {
        const uint32_t sA = sb + stage_byte;
        const uint32_t sB = sA + A_STAGE_U32 * 4;
        const uint32_t* gAt = gAt0 + t * KT;
        const uint32_t* gBt = gBt0 + t * KT;
        #pragma unroll
        for (int i = 0; i < 4; i++) cp_async16(sA + dstOff[i], gAt + srcOff[i]);
        #pragma unroll
        for (int i = 0; i < 4; i++) cp_async16(sB + dstOff[i], gBt + srcOff[i]);
    };

    // ---- hoisted fragment base addresses ----
    // All of a thread's fragment rows share parity p=(lid>>2)&1, so the
    // swizzled column is c0 = kq + (p<<2) for ks2=0 and c0^4 for ks2=1.
    const int gid = lid >> 2, kq = lid & 3;
    const int p = gid & 1;
    const uint32_t c0 = (uint32_t)(kq + (p << 2)) * 16;      // bytes
    const uint32_t c1 = c0 ^ 64;
    const int arow = wr * 32 + gid;        // + mt*16 + h*8 (even adds)
    const int brow = wc * 64 + gid;        // + nt*8
    // base addr per stage, per ks2 (A and B planes)
    uint32_t bA[STAGES][2], bB[STAGES][2];
    #pragma unroll
    for (int s = 0; s < STAGES; s++) {
        uint32_t stA = sb + s * STAGE_BYTES;
        uint32_t stB = stA + A_STAGE_U32 * 4;
        bA[s][0] = stA + (uint32_t)(arow * 128) + c0;
        bA[s][1] = stA + (uint32_t)(arow * 128) + c1;
        bB[s][0] = stB + (uint32_t)(brow * 128) + c0;
        bB[s][1] = stB + (uint32_t)(brow * 128) + c1;
    }

    float acc[2][8][4];
    #pragma unroll
    for (int mt = 0; mt < 2; mt++)
        #pragma unroll
        for (int nt = 0; nt < 8; nt++)
            #pragma unroll
            for (int c = 0; c < 4; c++) acc[mt][nt][c] = 0.0f;

    load_tile(0, 0); CP_COMMIT();
    load_tile(1, STAGE_BYTES); CP_COMMIT();

    // one pipeline iteration; cs is COMPILE-TIME in all call sites
    auto iter = [&](int t, int cs) {
        CP_WAIT1();
        __syncthreads();
        const int tl = t + 2;
        if (tl < NUM_KT) {
            const int lsb = (cs + 2) % STAGES;          // stage of tile t+2
            load_tile(tl, (uint32_t)(lsb * STAGE_BYTES));
        }
        CP_COMMIT();

        #pragma unroll
        for (int ks2 = 0; ks2 < 2; ks2++) {
            uint4 Ar[2][2];
            #pragma unroll
            for (int mt = 0; mt < 2; mt++)
                #pragma unroll
                for (int h = 0; h < 2; h++)
                    lds128(Ar[mt][h], bA[cs][ks2] + (uint32_t)(mt * 2048 + h * 1024));
            #pragma unroll
            for (int ng = 0; ng < 2; ng++) {
                uint4 Br[4];
                #pragma unroll
                for (int j = 0; j < 4; j++)
                    lds128(Br[j], bB[cs][ks2] + (uint32_t)((ng * 4 + j) * 1024));
                #pragma unroll
                for (int sub = 0; sub < 2; sub++) {
                    #pragma unroll
                    for (int mt = 0; mt < 2; mt++) {
                        uint32_t a[4];
                        a[0] = (&Ar[mt][0].x)[2 * sub];
                        a[1] = (&Ar[mt][1].x)[2 * sub];
                        a[2] = (&Ar[mt][0].x)[2 * sub + 1];
                        a[3] = (&Ar[mt][1].x)[2 * sub + 1];
                        #pragma unroll
                        for (int j = 0; j < 4; j++) {
                            uint32_t b[2];
                            b[0] = (&Br[j].x)[2 * sub];
                            b[1] = (&Br[j].x)[2 * sub + 1];
                            mma_tf32(acc[mt][ng * 4 + j], a, b);
                        }
                    }
                }
            }
        }
    };

    // 128 iterations = 42 triples + 2 tail; stage index compile-time throughout
    int kt = 0;
    #pragma unroll 1
    for (int blk = 0; blk < 42; blk++) {
        iter(kt + 0, 0);
        iter(kt + 1, 1);
        iter(kt + 2, 2);
        kt += 3;
    }
    iter(126, 0);
    iter(127, 1);

    // fused bias epilogue
    const int gcol0 = bn * NT + wc * 64 + 2 * kq;
    #pragma unroll
    for (int mt = 0; mt < 2; mt++) {
        #pragma unroll
        for (int half = 0; half < 2; half++) {
            const int grow = bm * MT + wr * 32 + mt * 16 + gid + half * 8;
            float* op = out + (size_t)grow * N_DIM + gcol0;
            #pragma unroll
            for (int nt = 0; nt < 8; nt++) {
                const int gc = gcol0 + nt * 8;
                float2 o;
                o.x = acc[mt][nt][half * 2 + 0] + __ldg(bias + gc);
                o.y = acc[mt][nt][half * 2 + 1] + __ldg(bias + gc + 1);
                *reinterpret_cast<float2*>(op + nt * 8) = o;
            }
        }
    }
}

// ---------------------------------------------------------------- launcher
extern "C" void kernel_launch(void* const* d_in, const int* in_sizes, int n_in,
                              void* d_out, int out_size) {
    // Resolve inputs BY SIZE (unique element counts).
    const float* x      = nullptr;
    const void*  qw     = nullptr;
    const float* scales = nullptr;
    const float* bias   = nullptr;
    for (int i = 0; i < n_in; i++) {
        switch (in_sizes[i]) {
            case 33554432: x      = (const float*)d_in[i]; break;
            case 16777216: qw     = d_in[i];               break;
            case 262144:   scales = (const float*)d_in[i]; break;
            case 4096:     bias   = (const float*)d_in[i]; break;
            default: break;
        }
    }
    float* out = (float*)d_out;

    uint32_t* gA; cudaGetSymbolAddress((void**)&gA, g_xa);
    uint32_t* gB; cudaGetSymbolAddress((void**)&gB, g_wb);

    detect_wtype_kernel<<<1, 256>>>((const int*)qw);
    cvt_x_kernel<<<4096, 256>>>((const float4*)x, (uint4*)gA, (M_DIM * K_DIM) / 16);
    dequant_w_kernel<<<2048, 256>>>(qw, scales, (uint4*)gB, (N_DIM * K_DIM) / 16);

    cudaFuncSetAttribute(gemm_tf32_kernel, cudaFuncAttributeMaxDynamicSharedMemorySize, SMEM_TOTAL);
    dim3 grid(N_DIM / NT, M_DIM / MT);   // (32, 64)
    gemm_tf32_kernel<<<grid, 256, SMEM_TOTAL>>>(gA, gB, bias, out);
}